// round 12
// baseline (speedup 1.0000x reference)
#include <cuda_runtime.h>
#include <cuda_fp16.h>
#include <stdint.h>
#include <math.h>

#define SEQ    2048
#define DH     64
#define NBH    32
#define DM     1024
#define NROWS  4096
#define STRB   144          // smem row stride in bytes (72 halves)
#define TILEB  (128 * STRB) // one 128x64 fp16 tile (padded)
#define HTILEB (64 * STRB)  // one 64x64 fp16 tile

// ---------------- global scratch (fp16) ----------------
__device__ __half g_Qf[NBH * SEQ * DH];
__device__ __half g_Kf[NBH * SEQ * DH];
__device__ __half g_Vf[NBH * SEQ * DH];
__device__ __half g_Wf[DM * DM];
__device__ __half g_xf[NROWS * DM];

// ---------------- helpers ----------------
__device__ __forceinline__ uint32_t smem_u32(const void* p) {
    uint32_t a;
    asm("{ .reg .u64 t; cvta.to.shared.u64 t, %1; cvt.u32.u64 %0, t; }" : "=r"(a) : "l"(p));
    return a;
}
__device__ __forceinline__ uint32_t lds_addr(uint32_t base, int r0, int c0, int lane) {
    return base + (uint32_t)(r0 + (lane & 15)) * STRB + (uint32_t)(c0 + ((lane >> 4) << 3)) * 2u;
}
__device__ __forceinline__ void ldsm4(uint32_t* r, uint32_t addr) {
    asm volatile("ldmatrix.sync.aligned.m8n8.x4.shared.b16 {%0,%1,%2,%3}, [%4];"
                 : "=r"(r[0]), "=r"(r[1]), "=r"(r[2]), "=r"(r[3]) : "r"(addr));
}
__device__ __forceinline__ void ldsm4t(uint32_t* r, uint32_t addr) {
    asm volatile("ldmatrix.sync.aligned.m8n8.x4.trans.shared.b16 {%0,%1,%2,%3}, [%4];"
                 : "=r"(r[0]), "=r"(r[1]), "=r"(r[2]), "=r"(r[3]) : "r"(addr));
}
__device__ __forceinline__ void mma16816(float* c, const uint32_t* a, uint32_t b0, uint32_t b1) {
    asm volatile("mma.sync.aligned.m16n8k16.row.col.f32.f16.f16.f32 "
                 "{%0,%1,%2,%3}, {%4,%5,%6,%7}, {%8,%9}, {%0,%1,%2,%3};"
                 : "+f"(c[0]), "+f"(c[1]), "+f"(c[2]), "+f"(c[3])
                 : "r"(a[0]), "r"(a[1]), "r"(a[2]), "r"(a[3]), "r"(b0), "r"(b1));
}
__device__ __forceinline__ uint32_t pack2(float f0, float f1) {
    __half2 h = __floats2half2_rn(f0, f1);
    return *(uint32_t*)&h;
}
__device__ __forceinline__ void cp16(uint32_t dst, const void* src) {
    asm volatile("cp.async.ca.shared.global [%0], [%1], 16;" :: "r"(dst), "l"(src));
}
#define CP_COMMIT() asm volatile("cp.async.commit_group;" ::: "memory")
#define CP_WAIT0()  asm volatile("cp.async.wait_group 0;" ::: "memory")

// stage a [rows x 64 fp16] tile into padded smem (sync loads)
__device__ __forceinline__ void stage_tile(char* dst, const __half* __restrict__ src,
                                           int gstride, int rows) {
    for (int i = threadIdx.x; i < rows * 8; i += 256) {
        const int r = i >> 3, s = i & 7;
        *(uint4*)(dst + r * STRB + s * 16) = *(const uint4*)(src + (size_t)r * gstride + s * 8);
    }
}
// async version
__device__ __forceinline__ void stage_async(uint32_t dst, const __half* __restrict__ src,
                                            int gstride, int rows) {
    for (int i = threadIdx.x; i < rows * 8; i += 256) {
        const int r = i >> 3, s = i & 7;
        cp16(dst + (uint32_t)(r * STRB + s * 16), src + (size_t)r * gstride + s * 8);
    }
}

// ---------------- preprocessing: fused vectorized convert ----------------
#define NQ (NBH * SEQ * DH)
__global__ void conv_all(const float* __restrict__ Q, const float* __restrict__ K,
                         const float* __restrict__ V, const float* __restrict__ W) {
    const int total8 = (3 * NQ + DM * DM) / 8;
    for (int i = blockIdx.x * blockDim.x + threadIdx.x; i < total8; i += gridDim.x * blockDim.x) {
        const int base = i * 8;
        const float* src; __half* dst; int idx;
        if (base < NQ)            { src = Q; dst = g_Qf; idx = base; }
        else if (base < 2 * NQ)   { src = K; dst = g_Kf; idx = base - NQ; }
        else if (base < 3 * NQ)   { src = V; dst = g_Vf; idx = base - 2 * NQ; }
        else                      { src = W; dst = g_Wf; idx = base - 3 * NQ; }
        const float4 a = *(const float4*)(src + idx);
        const float4 b = *(const float4*)(src + idx + 4);
        uint4 o;
        o.x = pack2(a.x, a.y); o.y = pack2(a.z, a.w);
        o.z = pack2(b.x, b.y); o.w = pack2(b.z, b.w);
        *(uint4*)(dst + idx) = o;
    }
}

// ---------------- flash attention: kc-pair phase-pipelined ----------------
// smem: [K0][V0][K1][V1] = 72KB; 2 CTAs/SM
__global__ void __launch_bounds__(256, 2) attn_mma(const float* __restrict__ mask) {
    extern __shared__ char smem[];
    const uint32_t sb = smem_u32(smem);
    const uint32_t bK[2] = { sb,             sb + 2 * TILEB };
    const uint32_t bV[2] = { sb + TILEB,     sb + 3 * TILEB };

    const int tid = threadIdx.x;
    const int wid = tid >> 5, lane = tid & 31;
    const int grp = lane >> 2, qd = (lane & 3) * 2;
    const int q0  = blockIdx.x * 128;
    const int bh  = blockIdx.y;
    const size_t hbase = (size_t)bh * (SEQ * DH);
    const __half* Kh = g_Kf + hbase;
    const __half* Vh = g_Vf + hbase;

    // stage Q through buffer 0; keep persistent A fragments
    uint32_t qa[4][4];
    stage_tile(smem, g_Qf + hbase + (size_t)q0 * DH, 64, 128);
    __syncthreads();
#pragma unroll
    for (int dc = 0; dc < 4; ++dc) ldsm4(qa[dc], lds_addr(bK[0], wid * 16, dc * 16, lane));
    __syncthreads();

    // prefetch tile 0
    stage_async(bK[0], Kh, 64, 128);
    stage_async(bV[0], Vh, 64, 128);
    CP_COMMIT();

    float o[8][4];
#pragma unroll
    for (int n = 0; n < 8; ++n)
#pragma unroll
        for (int j = 0; j < 4; ++j) o[n][j] = 0.0f;
    float sum0 = 0.0f, sum1 = 0.0f;

    const float* mbase = mask + (size_t)(q0 + wid * 16 + grp) * SEQ + qd;

    for (int t = 0; t < SEQ / 128; ++t) {
        CP_WAIT0();
        __syncthreads();           // tile t resident; all warps done with buf[(t+1)&1]
        if (t + 1 < SEQ / 128) {   // prefetch t+1 under compute of t
            const size_t nkoff = (size_t)(t + 1) * 128 * DH;
            stage_async(bK[(t + 1) & 1], Kh + nkoff, 64, 128);
            stage_async(bV[(t + 1) & 1], Vh + nkoff, 64, 128);
        }
        CP_COMMIT();

        const uint32_t cK = bK[t & 1], cV = bV[t & 1];

#pragma unroll
        for (int p = 0; p < 4; ++p) {
            const int kcA = 2 * p, kcB = 2 * p + 1;

            // ---- mask loads for both halves (land under the S phases) ----
            const float* rowA = mbase + t * 128 + kcA * 16;
            const float* rowB = rowA + 16;
            const float2 a0 = __ldg((const float2*)(rowA));
            const float2 a1 = __ldg((const float2*)(rowA + 8));
            const float2 a2 = __ldg((const float2*)(rowA + 8 * SEQ));
            const float2 a3 = __ldg((const float2*)(rowA + 8 * SEQ + 8));
            const float2 b0 = __ldg((const float2*)(rowB));
            const float2 b1 = __ldg((const float2*)(rowB + 8));
            const float2 b2 = __ldg((const float2*)(rowB + 8 * SEQ));
            const float2 b3 = __ldg((const float2*)(rowB + 8 * SEQ + 8));

            // ---- S phase A ----
            float c0A[4] = {0, 0, 0, 0}, c1A[4] = {0, 0, 0, 0};
            {
                uint32_t kb[4][4];
#pragma unroll
                for (int dc = 0; dc < 4; ++dc) ldsm4(kb[dc], lds_addr(cK, kcA * 16, dc * 16, lane));
#pragma unroll
                for (int dc = 0; dc < 4; ++dc) {
                    mma16816(c0A, qa[dc], kb[dc][0], kb[dc][2]);
                    mma16816(c1A, qa[dc], kb[dc][1], kb[dc][3]);
                }
            }
            // ---- S phase B (independent; hides A's MMA latency) ----
            float c0B[4] = {0, 0, 0, 0}, c1B[4] = {0, 0, 0, 0};
            {
                uint32_t kb[4][4];
#pragma unroll
                for (int dc = 0; dc < 4; ++dc) ldsm4(kb[dc], lds_addr(cK, kcB * 16, dc * 16, lane));
#pragma unroll
                for (int dc = 0; dc < 4; ++dc) {
                    mma16816(c0B, qa[dc], kb[dc][0], kb[dc][2]);
                    mma16816(c1B, qa[dc], kb[dc][1], kb[dc][3]);
                }
            }

            // ---- softmax A ----
            const float pA00 = __expf(c0A[0] * 0.125f + a0.x);
            const float pA01 = __expf(c0A[1] * 0.125f + a0.y);
            const float pA02 = __expf(c0A[2] * 0.125f + a2.x);
            const float pA03 = __expf(c0A[3] * 0.125f + a2.y);
            const float pA10 = __expf(c1A[0] * 0.125f + a1.x);
            const float pA11 = __expf(c1A[1] * 0.125f + a1.y);
            const float pA12 = __expf(c1A[2] * 0.125f + a3.x);
            const float pA13 = __expf(c1A[3] * 0.125f + a3.y);
            uint32_t paA[4];
            paA[0] = pack2(pA00, pA01); paA[1] = pack2(pA02, pA03);
            paA[2] = pack2(pA10, pA11); paA[3] = pack2(pA12, pA13);

            // ---- softmax B (hides A's exp->pack latency) ----
            const float pB00 = __expf(c0B[0] * 0.125f + b0.x);
            const float pB01 = __expf(c0B[1] * 0.125f + b0.y);
            const float pB02 = __expf(c0B[2] * 0.125f + b2.x);
            const float pB03 = __expf(c0B[3] * 0.125f + b2.y);
            const float pB10 = __expf(c1B[0] * 0.125f + b1.x);
            const float pB11 = __expf(c1B[1] * 0.125f + b1.y);
            const float pB12 = __expf(c1B[2] * 0.125f + b3.x);
            const float pB13 = __expf(c1B[3] * 0.125f + b3.y);
            uint32_t paB[4];
            paB[0] = pack2(pB00, pB01); paB[1] = pack2(pB02, pB03);
            paB[2] = pack2(pB10, pB11); paB[3] = pack2(pB12, pB13);

            sum0 += (pA00 + pA01 + pA10 + pA11) + (pB00 + pB01 + pB10 + pB11);
            sum1 += (pA02 + pA03 + pA12 + pA13) + (pB02 + pB03 + pB12 + pB13);

            // ---- PV phase A ----
            {
                uint32_t vb[4][4];
#pragma unroll
                for (int g = 0; g < 4; ++g) ldsm4t(vb[g], lds_addr(cV, kcA * 16, g * 16, lane));
#pragma unroll
                for (int g = 0; g < 4; ++g) {
                    mma16816(o[2 * g],     paA, vb[g][0], vb[g][1]);
                    mma16816(o[2 * g + 1], paA, vb[g][2], vb[g][3]);
                }
            }
            // ---- PV phase B ----
            {
                uint32_t vb[4][4];
#pragma unroll
                for (int g = 0; g < 4; ++g) ldsm4t(vb[g], lds_addr(cV, kcB * 16, g * 16, lane));
#pragma unroll
                for (int g = 0; g < 4; ++g) {
                    mma16816(o[2 * g],     paB, vb[g][0], vb[g][1]);
                    mma16816(o[2 * g + 1], paB, vb[g][2], vb[g][3]);
                }
            }
        }
        __syncthreads();           // done reading buf[t&1] before t+2 prefetch overwrites it
    }

    // ---- finalize: quad row sums, divide, write x ----
    sum0 += __shfl_xor_sync(0xffffffffu, sum0, 1);
    sum0 += __shfl_xor_sync(0xffffffffu, sum0, 2);
    sum1 += __shfl_xor_sync(0xffffffffu, sum1, 1);
    sum1 += __shfl_xor_sync(0xffffffffu, sum1, 2);
    const float inv0 = 1.0f / sum0, inv1 = 1.0f / sum1;

    const size_t r0o = hbase + (size_t)(q0 + wid * 16 + grp) * DH + qd;
    const size_t r1o = r0o + 8 * DH;
#pragma unroll
    for (int n = 0; n < 8; ++n) {
        *(uint32_t*)(g_xf + r0o + n * 8) = pack2(o[n][0] * inv0, o[n][1] * inv0);
        *(uint32_t*)(g_xf + r1o + n * 8) = pack2(o[n][2] * inv1, o[n][3] * inv1);
    }
}

// ---------------- output projection: out = xf @ Wf^T + b ----------------
// smem: [A0][B0][A1][B1] = 54KB; 2 CTAs/SM
__global__ void __launch_bounds__(256, 2) gemm_mma(const float* __restrict__ bias,
                                                   float* __restrict__ out) {
    extern __shared__ char smem[];
    const uint32_t sb = smem_u32(smem);
    const uint32_t bA[2] = { sb,                     sb + TILEB + HTILEB };
    const uint32_t bB[2] = { sb + TILEB,             sb + 2 * TILEB + HTILEB };

    const int tid = threadIdx.x;
    const int wid = tid >> 5, lane = tid & 31;
    const int grp = lane >> 2, qd = (lane & 3) * 2;
    const int i0 = blockIdx.x * 128;
    const int j0 = blockIdx.y * 64;

    float o[8][4];
#pragma unroll
    for (int n = 0; n < 8; ++n)
#pragma unroll
        for (int j = 0; j < 4; ++j) o[n][j] = 0.0f;

    stage_async(bA[0], g_xf + (size_t)i0 * DM, DM, 128);
    stage_async(bB[0], g_Wf + (size_t)j0 * DM, DM, 64);
    CP_COMMIT();

    for (int ks = 0; ks < DM / 64; ++ks) {
        CP_WAIT0();
        __syncthreads();
        if (ks + 1 < DM / 64) {
            stage_async(bA[(ks + 1) & 1], g_xf + (size_t)i0 * DM + (ks + 1) * 64, DM, 128);
            stage_async(bB[(ks + 1) & 1], g_Wf + (size_t)j0 * DM + (ks + 1) * 64, DM, 64);
        }
        CP_COMMIT();

        const uint32_t cA = bA[ks & 1], cB = bB[ks & 1];
        uint32_t aa[4][4];
#pragma unroll
        for (int dc = 0; dc < 4; ++dc) ldsm4(aa[dc], lds_addr(cA, wid * 16, dc * 16, lane));
        // dc-outer / nb-inner: all 8 o-chains touched round-robin (depth-1 visits)
#pragma unroll
        for (int dc = 0; dc < 4; ++dc) {
#pragma unroll
            for (int nb = 0; nb < 4; ++nb) {
                uint32_t bb[4];
                ldsm4(bb, lds_addr(cB, nb * 16, dc * 16, lane));
                mma16816(o[2 * nb],     aa[dc], bb[0], bb[2]);
                mma16816(o[2 * nb + 1], aa[dc], bb[1], bb[3]);
            }
        }
        __syncthreads();
    }

    const int r0 = i0 + wid * 16 + grp;
#pragma unroll
    for (int n = 0; n < 8; ++n) {
        const int col = j0 + n * 8 + qd;
        const float2 bb = __ldg((const float2*)&bias[col]);
        float2 v0 = make_float2(o[n][0] + bb.x, o[n][1] + bb.y);
        float2 v1 = make_float2(o[n][2] + bb.x, o[n][3] + bb.y);
        *(float2*)&out[(size_t)r0 * DM + col] = v0;
        *(float2*)&out[(size_t)(r0 + 8) * DM + col] = v1;
    }
}

// ---------------- launch ----------------
extern "C" void kernel_launch(void* const* d_in, const int* in_sizes, int n_in,
                              void* d_out, int out_size) {
    const float* Q    = (const float*)d_in[0];
    const float* K    = (const float*)d_in[1];
    const float* V    = (const float*)d_in[2];
    const float* mask = (const float*)d_in[3];
    const float* W    = (const float*)d_in[4];
    const float* b    = (const float*)d_in[5];
    float* out = (float*)d_out;

    cudaFuncSetAttribute(attn_mma, cudaFuncAttributeMaxDynamicSharedMemorySize, 4 * TILEB);
    cudaFuncSetAttribute(gemm_mma, cudaFuncAttributeMaxDynamicSharedMemorySize,
                         2 * (TILEB + HTILEB));

    conv_all<<<4096, 256>>>(Q, K, V, W);
    attn_mma<<<dim3(SEQ / 128, NBH), 256, 4 * TILEB>>>(mask);
    gemm_mma<<<dim3(NROWS / 128, DM / 64), 256, 2 * (TILEB + HTILEB)>>>(b, out);
}

// round 13
// speedup vs baseline: 1.1527x; 1.1527x over previous
#include <cuda_runtime.h>
#include <cuda_fp16.h>
#include <stdint.h>
#include <math.h>

#define SEQ    2048
#define DH     64
#define NBH    32
#define DM     1024
#define NROWS  4096
#define STRB   144          // smem row stride in bytes (72 halves)
#define TILEB  (128 * STRB) // one 128x64 fp16 tile (padded)
#define HTILEB (64 * STRB)  // one 64x64 fp16 tile

// ---------------- global scratch (fp16) + dataflow flags ----------------
__device__ __half g_Qf[NBH * SEQ * DH];
__device__ __half g_Kf[NBH * SEQ * DH];
__device__ __half g_Vf[NBH * SEQ * DH];
__device__ __half g_Wf[DM * DM];
__device__ __half g_xf[NROWS * DM];
__device__ int g_headcnt[NBH];   // # attn blocks done for head h

// ---------------- helpers ----------------
__device__ __forceinline__ uint32_t smem_u32(const void* p) {
    uint32_t a;
    asm("{ .reg .u64 t; cvta.to.shared.u64 t, %1; cvt.u32.u64 %0, t; }" : "=r"(a) : "l"(p));
    return a;
}
__device__ __forceinline__ uint32_t lds_addr(uint32_t base, int r0, int c0, int lane) {
    return base + (uint32_t)(r0 + (lane & 15)) * STRB + (uint32_t)(c0 + ((lane >> 4) << 3)) * 2u;
}
__device__ __forceinline__ void ldsm4(uint32_t* r, uint32_t addr) {
    asm volatile("ldmatrix.sync.aligned.m8n8.x4.shared.b16 {%0,%1,%2,%3}, [%4];"
                 : "=r"(r[0]), "=r"(r[1]), "=r"(r[2]), "=r"(r[3]) : "r"(addr));
}
__device__ __forceinline__ void ldsm4t(uint32_t* r, uint32_t addr) {
    asm volatile("ldmatrix.sync.aligned.m8n8.x4.trans.shared.b16 {%0,%1,%2,%3}, [%4];"
                 : "=r"(r[0]), "=r"(r[1]), "=r"(r[2]), "=r"(r[3]) : "r"(addr));
}
__device__ __forceinline__ void mma16816(float* c, const uint32_t* a, uint32_t b0, uint32_t b1) {
    asm volatile("mma.sync.aligned.m16n8k16.row.col.f32.f16.f16.f32 "
                 "{%0,%1,%2,%3}, {%4,%5,%6,%7}, {%8,%9}, {%0,%1,%2,%3};"
                 : "+f"(c[0]), "+f"(c[1]), "+f"(c[2]), "+f"(c[3])
                 : "r"(a[0]), "r"(a[1]), "r"(a[2]), "r"(a[3]), "r"(b0), "r"(b1));
}
__device__ __forceinline__ uint32_t pack2(float f0, float f1) {
    __half2 h = __floats2half2_rn(f0, f1);
    return *(uint32_t*)&h;
}
__device__ __forceinline__ void cp16(uint32_t dst, const void* src) {
    asm volatile("cp.async.ca.shared.global [%0], [%1], 16;" :: "r"(dst), "l"(src));
}
#define CP_COMMIT() asm volatile("cp.async.commit_group;" ::: "memory")
#define CP_WAIT0()  asm volatile("cp.async.wait_group 0;" ::: "memory")

__device__ __forceinline__ void stage_tile(char* dst, const __half* __restrict__ src,
                                           int gstride, int rows) {
    for (int i = threadIdx.x; i < rows * 8; i += 256) {
        const int r = i >> 3, s = i & 7;
        *(uint4*)(dst + r * STRB + s * 16) = *(const uint4*)(src + (size_t)r * gstride + s * 8);
    }
}
__device__ __forceinline__ void stage_async(uint32_t dst, const __half* __restrict__ src,
                                            int gstride, int rows) {
    for (int i = threadIdx.x; i < rows * 8; i += 256) {
        const int r = i >> 3, s = i & 7;
        cp16(dst + (uint32_t)(r * STRB + s * 16), src + (size_t)r * gstride + s * 8);
    }
}

// ---------------- reset (graph-replay determinism) ----------------
__global__ void reset_flags() {
    if (threadIdx.x < NBH) g_headcnt[threadIdx.x] = 0;
}

// ---------------- preprocessing: fused vectorized convert ----------------
#define NQ (NBH * SEQ * DH)
__global__ void conv_all(const float* __restrict__ Q, const float* __restrict__ K,
                         const float* __restrict__ V, const float* __restrict__ W) {
    const int total8 = (3 * NQ + DM * DM) / 8;
    for (int i = blockIdx.x * blockDim.x + threadIdx.x; i < total8; i += gridDim.x * blockDim.x) {
        const int base = i * 8;
        const float* src; __half* dst; int idx;
        if (base < NQ)            { src = Q; dst = g_Qf; idx = base; }
        else if (base < 2 * NQ)   { src = K; dst = g_Kf; idx = base - NQ; }
        else if (base < 3 * NQ)   { src = V; dst = g_Vf; idx = base - 2 * NQ; }
        else                      { src = W; dst = g_Wf; idx = base - 3 * NQ; }
        const float4 a = *(const float4*)(src + idx);
        const float4 b = *(const float4*)(src + idx + 4);
        uint4 o;
        o.x = pack2(a.x, a.y); o.y = pack2(a.z, a.w);
        o.z = pack2(b.x, b.y); o.w = pack2(b.z, b.w);
        *(uint4*)(dst + idx) = o;
    }
}

// ---------------- fused: attn blocks [0,512) | gemm blocks [512,1024) ----------------
__global__ void __launch_bounds__(256, 2) attn_gemm(const float* __restrict__ mask,
                                                    const float* __restrict__ bias,
                                                    float* __restrict__ out) {
    extern __shared__ char smem[];
    const uint32_t sb = smem_u32(smem);
    const int blk = blockIdx.x;
    const int tid = threadIdx.x;
    const int wid = tid >> 5, lane = tid & 31;
    const int grp = lane >> 2, qd = (lane & 3) * 2;

    if (blk < 512) {
        // ================= attention (round-9 body) =================
        const int bh = blk >> 4;          // head-major: head 0 completes first
        const int q0 = (blk & 15) * 128;
        const size_t hbase = (size_t)bh * (SEQ * DH);
        const __half* Kh = g_Kf + hbase;
        const __half* Vh = g_Vf + hbase;

        const uint32_t bK[2] = { sb,         sb + 2 * TILEB };
        const uint32_t bV[2] = { sb + TILEB, sb + 3 * TILEB };

        uint32_t qa[4][4];
        stage_tile(smem, g_Qf + hbase + (size_t)q0 * DH, 64, 128);
        __syncthreads();
#pragma unroll
        for (int dc = 0; dc < 4; ++dc) ldsm4(qa[dc], lds_addr(bK[0], wid * 16, dc * 16, lane));
        __syncthreads();

        stage_async(bK[0], Kh, 64, 128);
        stage_async(bV[0], Vh, 64, 128);
        CP_COMMIT();

        float o[8][4];
#pragma unroll
        for (int n = 0; n < 8; ++n)
#pragma unroll
            for (int j = 0; j < 4; ++j) o[n][j] = 0.0f;
        float sum0 = 0.0f, sum1 = 0.0f;

        const float* mbase = mask + (size_t)(q0 + wid * 16 + grp) * SEQ + qd;
        float2 mk0 = __ldg((const float2*)(mbase));
        float2 mk1 = __ldg((const float2*)(mbase + 8));
        float2 mk2 = __ldg((const float2*)(mbase + 8 * SEQ));
        float2 mk3 = __ldg((const float2*)(mbase + 8 * SEQ + 8));

        for (int t = 0; t < SEQ / 128; ++t) {
            CP_WAIT0();
            __syncthreads();
            if (t + 1 < SEQ / 128) {
                const size_t nkoff = (size_t)(t + 1) * 128 * DH;
                stage_async(bK[(t + 1) & 1], Kh + nkoff, 64, 128);
                stage_async(bV[(t + 1) & 1], Vh + nkoff, 64, 128);
            }
            CP_COMMIT();

            const uint32_t cK = bK[t & 1], cV = bV[t & 1];

#pragma unroll
            for (int kc = 0; kc < 8; ++kc) {
                const int nt  = (kc == 7) ? ((t < 15) ? t + 1 : t) : t;
                const int nkc = (kc + 1) & 7;
                const float* nrow = mbase + nt * 128 + nkc * 16;
                const float2 n0 = __ldg((const float2*)(nrow));
                const float2 n1 = __ldg((const float2*)(nrow + 8));
                const float2 n2 = __ldg((const float2*)(nrow + 8 * SEQ));
                const float2 n3 = __ldg((const float2*)(nrow + 8 * SEQ + 8));

                float c0[4] = {0, 0, 0, 0}, c1[4] = {0, 0, 0, 0};
                uint32_t kb[4][4];
#pragma unroll
                for (int dc = 0; dc < 4; ++dc) ldsm4(kb[dc], lds_addr(cK, kc * 16, dc * 16, lane));
#pragma unroll
                for (int dc = 0; dc < 4; ++dc) {
                    mma16816(c0, qa[dc], kb[dc][0], kb[dc][2]);
                    mma16816(c1, qa[dc], kb[dc][1], kb[dc][3]);
                }

                const float p00 = __expf(c0[0] * 0.125f + mk0.x);
                const float p01 = __expf(c0[1] * 0.125f + mk0.y);
                const float p02 = __expf(c0[2] * 0.125f + mk2.x);
                const float p03 = __expf(c0[3] * 0.125f + mk2.y);
                const float p10 = __expf(c1[0] * 0.125f + mk1.x);
                const float p11 = __expf(c1[1] * 0.125f + mk1.y);
                const float p12 = __expf(c1[2] * 0.125f + mk3.x);
                const float p13 = __expf(c1[3] * 0.125f + mk3.y);
                sum0 += p00 + p01 + p10 + p11;
                sum1 += p02 + p03 + p12 + p13;
                mk0 = n0; mk1 = n1; mk2 = n2; mk3 = n3;

                uint32_t pa[4];
                pa[0] = pack2(p00, p01); pa[1] = pack2(p02, p03);
                pa[2] = pack2(p10, p11); pa[3] = pack2(p12, p13);

                uint32_t vb[4][4];
#pragma unroll
                for (int g = 0; g < 4; ++g) ldsm4t(vb[g], lds_addr(cV, kc * 16, g * 16, lane));
#pragma unroll
                for (int g = 0; g < 4; ++g) {
                    mma16816(o[2 * g],     pa, vb[g][0], vb[g][1]);
                    mma16816(o[2 * g + 1], pa, vb[g][2], vb[g][3]);
                }
            }
            __syncthreads();
        }

        sum0 += __shfl_xor_sync(0xffffffffu, sum0, 1);
        sum0 += __shfl_xor_sync(0xffffffffu, sum0, 2);
        sum1 += __shfl_xor_sync(0xffffffffu, sum1, 1);
        sum1 += __shfl_xor_sync(0xffffffffu, sum1, 2);
        const float inv0 = 1.0f / sum0, inv1 = 1.0f / sum1;

        const size_t r0o = hbase + (size_t)(q0 + wid * 16 + grp) * DH + qd;
        const size_t r1o = r0o + 8 * DH;
#pragma unroll
        for (int n = 0; n < 8; ++n) {
            *(uint32_t*)(g_xf + r0o + n * 8) = pack2(o[n][0] * inv0, o[n][1] * inv0);
            *(uint32_t*)(g_xf + r1o + n * 8) = pack2(o[n][2] * inv1, o[n][3] * inv1);
        }
        // release: make x visible, then count this block for its head
        __threadfence();
        __syncthreads();
        if (tid == 0) atomicAdd(&g_headcnt[bh], 1);
        return;
    }

    // ================= output projection (round-9 body) =================
    {
        const int u  = blk - 512;
        const int g  = u >> 4;            // head-major: matches attn completion order
        const int j0 = (u & 15) * 64;
        const int i0 = g * 128;

        // acquire: head g's 16 attn blocks done
        if (tid == 0) {
            while (atomicAdd(&g_headcnt[g], 0) < 16) __nanosleep(200);
            __threadfence();
        }
        __syncthreads();

        const uint32_t bA[2] = { sb,         sb + TILEB + HTILEB };
        const uint32_t bB[2] = { sb + TILEB, sb + 2 * TILEB + HTILEB };

        float o[8][4];
#pragma unroll
        for (int n = 0; n < 8; ++n)
#pragma unroll
            for (int j = 0; j < 4; ++j) o[n][j] = 0.0f;

        stage_async(bA[0], g_xf + (size_t)i0 * DM, DM, 128);
        stage_async(bB[0], g_Wf + (size_t)j0 * DM, DM, 64);
        CP_COMMIT();

        for (int ks = 0; ks < DM / 64; ++ks) {
            CP_WAIT0();
            __syncthreads();
            if (ks + 1 < DM / 64) {
                stage_async(bA[(ks + 1) & 1], g_xf + (size_t)i0 * DM + (ks + 1) * 64, DM, 128);
                stage_async(bB[(ks + 1) & 1], g_Wf + (size_t)j0 * DM + (ks + 1) * 64, DM, 64);
            }
            CP_COMMIT();

            const uint32_t cA = bA[ks & 1], cB = bB[ks & 1];
            uint32_t aa[4][4];
#pragma unroll
            for (int dc = 0; dc < 4; ++dc) ldsm4(aa[dc], lds_addr(cA, wid * 16, dc * 16, lane));
#pragma unroll
            for (int dc = 0; dc < 4; ++dc) {
#pragma unroll
                for (int nb = 0; nb < 4; ++nb) {
                    uint32_t bb[4];
                    ldsm4(bb, lds_addr(cB, nb * 16, dc * 16, lane));
                    mma16816(o[2 * nb],     aa[dc], bb[0], bb[2]);
                    mma16816(o[2 * nb + 1], aa[dc], bb[1], bb[3]);
                }
            }
            __syncthreads();
        }

        const int r0 = i0 + wid * 16 + grp;
#pragma unroll
        for (int n = 0; n < 8; ++n) {
            const int col = j0 + n * 8 + qd;
            const float2 bb = __ldg((const float2*)&bias[col]);
            float2 v0 = make_float2(o[n][0] + bb.x, o[n][1] + bb.y);
            float2 v1 = make_float2(o[n][2] + bb.x, o[n][3] + bb.y);
            *(float2*)&out[(size_t)r0 * DM + col] = v0;
            *(float2*)&out[(size_t)(r0 + 8) * DM + col] = v1;
        }
    }
}

// ---------------- launch ----------------
extern "C" void kernel_launch(void* const* d_in, const int* in_sizes, int n_in,
                              void* d_out, int out_size) {
    const float* Q    = (const float*)d_in[0];
    const float* K    = (const float*)d_in[1];
    const float* V    = (const float*)d_in[2];
    const float* mask = (const float*)d_in[3];
    const float* W    = (const float*)d_in[4];
    const float* b    = (const float*)d_in[5];
    float* out = (float*)d_out;

    cudaFuncSetAttribute(attn_gemm, cudaFuncAttributeMaxDynamicSharedMemorySize, 4 * TILEB);

    reset_flags<<<1, 32>>>();
    conv_all<<<4096, 256>>>(Q, K, V, W);
    attn_gemm<<<1024, 256, 4 * TILEB>>>(mask, b, out);
}

// round 14
// speedup vs baseline: 1.1667x; 1.0121x over previous
#include <cuda_runtime.h>
#include <cuda_fp16.h>
#include <stdint.h>
#include <math.h>

#define SEQ    2048
#define DH     64
#define NBH    32
#define DM     1024
#define NROWS  4096
#define STRB   144          // smem row stride in bytes (72 halves)
#define TILEB  (128 * STRB) // one 128x64 fp16 tile (padded)
#define HTILEB (64 * STRB)  // one 64x64 fp16 tile

// ---------------- global scratch (fp16) + dataflow flags ----------------
__device__ __half g_Kf[NBH * SEQ * DH];
__device__ __half g_Vf[NBH * SEQ * DH];
__device__ __half g_Wf[DM * DM];
__device__ __half g_xf[NROWS * DM];
__device__ int g_headcnt[NBH];   // # attn blocks done for head h

// ---------------- helpers ----------------
__device__ __forceinline__ uint32_t smem_u32(const void* p) {
    uint32_t a;
    asm("{ .reg .u64 t; cvta.to.shared.u64 t, %1; cvt.u32.u64 %0, t; }" : "=r"(a) : "l"(p));
    return a;
}
__device__ __forceinline__ uint32_t lds_addr(uint32_t base, int r0, int c0, int lane) {
    return base + (uint32_t)(r0 + (lane & 15)) * STRB + (uint32_t)(c0 + ((lane >> 4) << 3)) * 2u;
}
__device__ __forceinline__ void ldsm4(uint32_t* r, uint32_t addr) {
    asm volatile("ldmatrix.sync.aligned.m8n8.x4.shared.b16 {%0,%1,%2,%3}, [%4];"
                 : "=r"(r[0]), "=r"(r[1]), "=r"(r[2]), "=r"(r[3]) : "r"(addr));
}
__device__ __forceinline__ void ldsm4t(uint32_t* r, uint32_t addr) {
    asm volatile("ldmatrix.sync.aligned.m8n8.x4.trans.shared.b16 {%0,%1,%2,%3}, [%4];"
                 : "=r"(r[0]), "=r"(r[1]), "=r"(r[2]), "=r"(r[3]) : "r"(addr));
}
__device__ __forceinline__ void mma16816(float* c, const uint32_t* a, uint32_t b0, uint32_t b1) {
    asm volatile("mma.sync.aligned.m16n8k16.row.col.f32.f16.f16.f32 "
                 "{%0,%1,%2,%3}, {%4,%5,%6,%7}, {%8,%9}, {%0,%1,%2,%3};"
                 : "+f"(c[0]), "+f"(c[1]), "+f"(c[2]), "+f"(c[3])
                 : "r"(a[0]), "r"(a[1]), "r"(a[2]), "r"(a[3]), "r"(b0), "r"(b1));
}
__device__ __forceinline__ uint32_t pack2(float f0, float f1) {
    __half2 h = __floats2half2_rn(f0, f1);
    return *(uint32_t*)&h;
}
__device__ __forceinline__ void cp16(uint32_t dst, const void* src) {
    asm volatile("cp.async.ca.shared.global [%0], [%1], 16;" :: "r"(dst), "l"(src));
}
#define CP_COMMIT() asm volatile("cp.async.commit_group;" ::: "memory")
#define CP_WAIT0()  asm volatile("cp.async.wait_group 0;" ::: "memory")

// stage a [128 x 64 fp32] tile into padded fp16 smem, converting on the fly
__device__ __forceinline__ void stage_tile_f32(char* dst, const float* __restrict__ src) {
    for (int i = threadIdx.x; i < 128 * 8; i += 256) {
        const int r = i >> 3, s = i & 7;
        const float4 a = *(const float4*)(src + (size_t)r * 64 + s * 8);
        const float4 b = *(const float4*)(src + (size_t)r * 64 + s * 8 + 4);
        uint4 o;
        o.x = pack2(a.x, a.y); o.y = pack2(a.z, a.w);
        o.z = pack2(b.x, b.y); o.w = pack2(b.z, b.w);
        *(uint4*)(dst + r * STRB + s * 16) = o;
    }
}
__device__ __forceinline__ void stage_async(uint32_t dst, const __half* __restrict__ src,
                                            int gstride, int rows) {
    for (int i = threadIdx.x; i < rows * 8; i += 256) {
        const int r = i >> 3, s = i & 7;
        cp16(dst + (uint32_t)(r * STRB + s * 16), src + (size_t)r * gstride + s * 8);
    }
}

// ---------------- preprocessing: K/V/W convert + flag reset ----------------
#define NQ (NBH * SEQ * DH)
__global__ void conv_all(const float* __restrict__ K, const float* __restrict__ V,
                         const float* __restrict__ W) {
    if (blockIdx.x == 0 && threadIdx.x < NBH) g_headcnt[threadIdx.x] = 0;
    const int total8 = (2 * NQ + DM * DM) / 8;
    for (int i = blockIdx.x * blockDim.x + threadIdx.x; i < total8; i += gridDim.x * blockDim.x) {
        const int base = i * 8;
        const float* src; __half* dst; int idx;
        if (base < NQ)            { src = K; dst = g_Kf; idx = base; }
        else if (base < 2 * NQ)   { src = V; dst = g_Vf; idx = base - NQ; }
        else                      { src = W; dst = g_Wf; idx = base - 2 * NQ; }
        const float4 a = *(const float4*)(src + idx);
        const float4 b = *(const float4*)(src + idx + 4);
        uint4 o;
        o.x = pack2(a.x, a.y); o.y = pack2(a.z, a.w);
        o.z = pack2(b.x, b.y); o.w = pack2(b.z, b.w);
        *(uint4*)(dst + idx) = o;
    }
}

// ---------------- fused: attn blocks [0,512) | gemm blocks [512,1024) ----------------
__global__ void __launch_bounds__(256, 2) attn_gemm(const float* __restrict__ Q,
                                                    const float* __restrict__ mask,
                                                    const float* __restrict__ bias,
                                                    float* __restrict__ out) {
    extern __shared__ char smem[];
    const uint32_t sb = smem_u32(smem);
    const int blk = blockIdx.x;
    const int tid = threadIdx.x;
    const int wid = tid >> 5, lane = tid & 31;
    const int grp = lane >> 2, qd = (lane & 3) * 2;

    if (blk < 512) {
        // ================= attention =================
        const int bh = blk >> 4;          // head-major: head 0 completes first
        const int q0 = (blk & 15) * 128;
        const size_t hbase = (size_t)bh * (SEQ * DH);
        const __half* Kh = g_Kf + hbase;
        const __half* Vh = g_Vf + hbase;

        const uint32_t bK[2] = { sb,         sb + 2 * TILEB };
        const uint32_t bV[2] = { sb + TILEB, sb + 3 * TILEB };

        // stage Q directly from fp32 (converted in place; used once, no scratch trip)
        uint32_t qa[4][4];
        stage_tile_f32(smem, Q + hbase + (size_t)q0 * DH);
        __syncthreads();
#pragma unroll
        for (int dc = 0; dc < 4; ++dc) ldsm4(qa[dc], lds_addr(bK[0], wid * 16, dc * 16, lane));
        __syncthreads();

        stage_async(bK[0], Kh, 64, 128);
        stage_async(bV[0], Vh, 64, 128);
        CP_COMMIT();

        float o[8][4];
#pragma unroll
        for (int n = 0; n < 8; ++n)
#pragma unroll
            for (int j = 0; j < 4; ++j) o[n][j] = 0.0f;
        float sum0 = 0.0f, sum1 = 0.0f;

        const float* mbase = mask + (size_t)(q0 + wid * 16 + grp) * SEQ + qd;
        float2 mk0 = __ldg((const float2*)(mbase));
        float2 mk1 = __ldg((const float2*)(mbase + 8));
        float2 mk2 = __ldg((const float2*)(mbase + 8 * SEQ));
        float2 mk3 = __ldg((const float2*)(mbase + 8 * SEQ + 8));

        for (int t = 0; t < SEQ / 128; ++t) {
            CP_WAIT0();
            __syncthreads();
            if (t + 1 < SEQ / 128) {
                const size_t nkoff = (size_t)(t + 1) * 128 * DH;
                stage_async(bK[(t + 1) & 1], Kh + nkoff, 64, 128);
                stage_async(bV[(t + 1) & 1], Vh + nkoff, 64, 128);
            }
            CP_COMMIT();

            const uint32_t cK = bK[t & 1], cV = bV[t & 1];

#pragma unroll
            for (int kc = 0; kc < 8; ++kc) {
                const int nt  = (kc == 7) ? ((t < 15) ? t + 1 : t) : t;
                const int nkc = (kc + 1) & 7;
                const float* nrow = mbase + nt * 128 + nkc * 16;
                const float2 n0 = __ldg((const float2*)(nrow));
                const float2 n1 = __ldg((const float2*)(nrow + 8));
                const float2 n2 = __ldg((const float2*)(nrow + 8 * SEQ));
                const float2 n3 = __ldg((const float2*)(nrow + 8 * SEQ + 8));

                float c0[4] = {0, 0, 0, 0}, c1[4] = {0, 0, 0, 0};
                uint32_t kb[4][4];
#pragma unroll
                for (int dc = 0; dc < 4; ++dc) ldsm4(kb[dc], lds_addr(cK, kc * 16, dc * 16, lane));
#pragma unroll
                for (int dc = 0; dc < 4; ++dc) {
                    mma16816(c0, qa[dc], kb[dc][0], kb[dc][2]);
                    mma16816(c1, qa[dc], kb[dc][1], kb[dc][3]);
                }

                const float p00 = __expf(c0[0] * 0.125f + mk0.x);
                const float p01 = __expf(c0[1] * 0.125f + mk0.y);
                const float p02 = __expf(c0[2] * 0.125f + mk2.x);
                const float p03 = __expf(c0[3] * 0.125f + mk2.y);
                const float p10 = __expf(c1[0] * 0.125f + mk1.x);
                const float p11 = __expf(c1[1] * 0.125f + mk1.y);
                const float p12 = __expf(c1[2] * 0.125f + mk3.x);
                const float p13 = __expf(c1[3] * 0.125f + mk3.y);
                sum0 += p00 + p01 + p10 + p11;
                sum1 += p02 + p03 + p12 + p13;
                mk0 = n0; mk1 = n1; mk2 = n2; mk3 = n3;

                uint32_t pa[4];
                pa[0] = pack2(p00, p01); pa[1] = pack2(p02, p03);
                pa[2] = pack2(p10, p11); pa[3] = pack2(p12, p13);

                uint32_t vb[4][4];
#pragma unroll
                for (int g = 0; g < 4; ++g) ldsm4t(vb[g], lds_addr(cV, kc * 16, g * 16, lane));
#pragma unroll
                for (int g = 0; g < 4; ++g) {
                    mma16816(o[2 * g],     pa, vb[g][0], vb[g][1]);
                    mma16816(o[2 * g + 1], pa, vb[g][2], vb[g][3]);
                }
            }
            __syncthreads();
        }

        sum0 += __shfl_xor_sync(0xffffffffu, sum0, 1);
        sum0 += __shfl_xor_sync(0xffffffffu, sum0, 2);
        sum1 += __shfl_xor_sync(0xffffffffu, sum1, 1);
        sum1 += __shfl_xor_sync(0xffffffffu, sum1, 2);
        const float inv0 = 1.0f / sum0, inv1 = 1.0f / sum1;

        const size_t r0o = hbase + (size_t)(q0 + wid * 16 + grp) * DH + qd;
        const size_t r1o = r0o + 8 * DH;
#pragma unroll
        for (int n = 0; n < 8; ++n) {
            *(uint32_t*)(g_xf + r0o + n * 8) = pack2(o[n][0] * inv0, o[n][1] * inv0);
            *(uint32_t*)(g_xf + r1o + n * 8) = pack2(o[n][2] * inv1, o[n][3] * inv1);
        }
        // release: make x visible, then count this block for its head
        __threadfence();
        __syncthreads();
        if (tid == 0) atomicAdd(&g_headcnt[bh], 1);
        return;
    }

    // ================= output projection =================
    {
        const int u  = blk - 512;
        const int g  = u >> 4;            // head-major: matches attn completion order
        const int j0 = (u & 15) * 64;
        const int i0 = g * 128;

        // acquire: head g's 16 attn blocks done
        if (tid == 0) {
            while (atomicAdd(&g_headcnt[g], 0) < 16) __nanosleep(200);
            __threadfence();
        }
        __syncthreads();

        const uint32_t bA[2] = { sb,         sb + TILEB + HTILEB };
        const uint32_t bB[2] = { sb + TILEB, sb + 2 * TILEB + HTILEB };

        float o[8][4];
#pragma unroll
        for (int n = 0; n < 8; ++n)
#pragma unroll
            for (int j = 0; j < 4; ++j) o[n][j] = 0.0f;

        stage_async(bA[0], g_xf + (size_t)i0 * DM, DM, 128);
        stage_async(bB[0], g_Wf + (size_t)j0 * DM, DM, 64);
        CP_COMMIT();

        for (int ks = 0; ks < DM / 64; ++ks) {
            CP_WAIT0();
            __syncthreads();
            if (ks + 1 < DM / 64) {
                stage_async(bA[(ks + 1) & 1], g_xf + (size_t)i0 * DM + (ks + 1) * 64, DM, 128);
                stage_async(bB[(ks + 1) & 1], g_Wf + (size_t)j0 * DM + (ks + 1) * 64, DM, 64);
            }
            CP_COMMIT();

            const uint32_t cA = bA[ks & 1], cB = bB[ks & 1];
            uint32_t aa[4][4];
#pragma unroll
            for (int dc = 0; dc < 4; ++dc) ldsm4(aa[dc], lds_addr(cA, wid * 16, dc * 16, lane));
#pragma unroll
            for (int dc = 0; dc < 4; ++dc) {
#pragma unroll
                for (int nb = 0; nb < 4; ++nb) {
                    uint32_t bb[4];
                    ldsm4(bb, lds_addr(cB, nb * 16, dc * 16, lane));
                    mma16816(o[2 * nb],     aa[dc], bb[0], bb[2]);
                    mma16816(o[2 * nb + 1], aa[dc], bb[1], bb[3]);
                }
            }
            __syncthreads();
        }

        const int r0 = i0 + wid * 16 + grp;
#pragma unroll
        for (int n = 0; n < 8; ++n) {
            const int col = j0 + n * 8 + qd;
            const float2 bb = __ldg((const float2*)&bias[col]);
            float2 v0 = make_float2(o[n][0] + bb.x, o[n][1] + bb.y);
            float2 v1 = make_float2(o[n][2] + bb.x, o[n][3] + bb.y);
            *(float2*)&out[(size_t)r0 * DM + col] = v0;
            *(float2*)&out[(size_t)(r0 + 8) * DM + col] = v1;
        }
    }
}

// ---------------- launch ----------------
extern "C" void kernel_launch(void* const* d_in, const int* in_sizes, int n_in,
                              void* d_out, int out_size) {
    const float* Q    = (const float*)d_in[0];
    const float* K    = (const float*)d_in[1];
    const float* V    = (const float*)d_in[2];
    const float* mask = (const float*)d_in[3];
    const float* W    = (const float*)d_in[4];
    const float* b    = (const float*)d_in[5];
    float* out = (float*)d_out;

    cudaFuncSetAttribute(attn_gemm, cudaFuncAttributeMaxDynamicSharedMemorySize, 4 * TILEB);

    conv_all<<<4096, 256>>>(K, V, W);
    attn_gemm<<<1024, 256, 4 * TILEB>>>(Q, mask, b, out);
}